// round 6
// baseline (speedup 1.0000x reference)
#include <cuda_runtime.h>
#include <math_constants.h>

#define HH 1024
#define WW 1024
#define NCH 48
#define RSTRIP 16
#define SLICES (HH / RSTRIP)   // 64 row-slices per channel

// Per-(channel, row-slice) max of raw |det|. Every slot is written on every
// run by pass 1, so no init kernel and no atomics are needed.
__device__ float g_bmax[NCH * SLICES];

// ---------------------------------------------------------------------------
// Pass 1: per-slice max of raw scores. No NMS, no output stores.
// Each thread: 8 score cols (gc..gc+7); x cols gc-1..gc+8.
// Own data = 2 aligned float4; +-1 halo via neighbor-lane shuffles.
// ---------------------------------------------------------------------------
__device__ __forceinline__ void ldrow10(const float* __restrict__ row, int gc,
                                        int lane, float u[10]) {
    float4 m0 = *reinterpret_cast<const float4*>(row + gc);
    float4 m1 = *reinterpret_cast<const float4*>(row + gc + 4);
    u[1] = m0.x; u[2] = m0.y; u[3] = m0.z; u[4] = m0.w;
    u[5] = m1.x; u[6] = m1.y; u[7] = m1.z; u[8] = m1.w;
    u[0] = __shfl_up_sync(0xffffffffu, u[8], 1);   // prev lane's gc+7 == our gc-1
    u[9] = __shfl_down_sync(0xffffffffu, u[1], 1); // next lane's gc   == our gc+8
    if (lane == 0)  u[0] = row[max(gc - 1, 0)];
    if (lane == 31) u[9] = row[min(gc + 8, WW - 1)];
}

__global__ __launch_bounds__(128)
void max_kernel(const float* __restrict__ x) {
    __shared__ float wmax[4];
    const int ch = blockIdx.y;
    const int y0 = blockIdx.x * RSTRIP;
    const int gc = threadIdx.x * 8;
    const int lane = threadIdx.x & 31;
    const float* __restrict__ xc = x + (size_t)ch * (HH * WW);

    float X[3][10];
    ldrow10(xc + max(y0 - 1, 0) * WW, gc, lane, X[0]);
    ldrow10(xc + y0 * WW, gc, lane, X[1]);

    float m = 0.0f;
    #pragma unroll
    for (int i = 0; i < RSTRIP; i++) {
        const int ry = min(y0 + i + 1, HH - 1);
        ldrow10(xc + ry * WW, gc, lane, X[(i + 2) % 3]);
        const float* a = X[i % 3];
        const float* b = X[(i + 1) % 3];
        const float* c = X[(i + 2) % 3];

        float A[10], B[10], C[10];
        #pragma unroll
        for (int k = 0; k < 10; k++) {
            float t = a[k] + c[k];
            A[k] = fmaf(2.0f, b[k], t);
            B[k] = fmaf(-2.0f, b[k], t);
            C[k] = a[k] - c[k];
        }
        #pragma unroll
        for (int j = 0; j < 8; j++) {
            float gxx = fmaf(-2.0f, A[j + 1], A[j] + A[j + 2]);
            float gyy = fmaf(2.0f, B[j + 1], B[j] + B[j + 2]);
            float gxy = C[j + 2] - C[j];
            m = fmaxf(m, fabsf(fmaf(gxx, gyy, -gxy * gxy)));
        }
    }

    #pragma unroll
    for (int off = 16; off > 0; off >>= 1)
        m = fmaxf(m, __shfl_xor_sync(0xffffffffu, m, off));
    if (lane == 0) wmax[threadIdx.x >> 5] = m;
    __syncthreads();
    if (threadIdx.x == 0) {
        m = fmaxf(fmaxf(wmax[0], wmax[1]), fmaxf(wmax[2], wmax[3]));
        g_bmax[ch * SLICES + blockIdx.x] = m;
    }
}

// ---------------------------------------------------------------------------
// Pass 2: scores + separable NMS + normalization, registers only.
// Each thread: 4 output cols (gc..gc+3); x cols gc-2..gc+5.
// Own data = 1 aligned float4; +-2 halo via neighbor-lane shuffles.
// ---------------------------------------------------------------------------
__device__ __forceinline__ void ldrow8(const float* __restrict__ row, int gc,
                                       int lane, int lcm2, int lcm1,
                                       int lcp4, int lcp5, float v[8]) {
    float4 m = *reinterpret_cast<const float4*>(row + gc);
    v[2] = m.x; v[3] = m.y; v[4] = m.z; v[5] = m.w;
    v[0] = __shfl_up_sync(0xffffffffu, v[4], 1);   // prev lane's gc+2 == our gc-2
    v[1] = __shfl_up_sync(0xffffffffu, v[5], 1);   // prev lane's gc+3 == our gc-1
    v[6] = __shfl_down_sync(0xffffffffu, v[2], 1); // next lane's gc   == our gc+4
    v[7] = __shfl_down_sync(0xffffffffu, v[3], 1); // next lane's gc+1 == our gc+5
    if (lane == 0)  { v[0] = row[lcm2]; v[1] = row[lcm1]; }
    if (lane == 31) { v[6] = row[lcp4]; v[7] = row[lcp5]; }
}

__global__ __launch_bounds__(256, 5)
void hessian_kernel(const float* __restrict__ x, float* __restrict__ out) {
    __shared__ float redsm[2];
    const int ch = blockIdx.y;
    const int y0 = blockIdx.x * RSTRIP;
    const int gc = threadIdx.x * 4;
    const int lane = threadIdx.x & 31;
    const float* __restrict__ xc = x + (size_t)ch * (HH * WW);
    float* __restrict__ oc = out + (size_t)ch * (HH * WW);

    // Reduce the 64 per-slice maxima for this channel (L2-hit loads).
    if (threadIdx.x < SLICES) {
        float v = g_bmax[ch * SLICES + threadIdx.x];
        #pragma unroll
        for (int off = 16; off > 0; off >>= 1)
            v = fmaxf(v, __shfl_xor_sync(0xffffffffu, v, off));
        if ((threadIdx.x & 31) == 0) redsm[threadIdx.x >> 5] = v;
    }
    __syncthreads();
    const float inv = 1.0f / fmaxf(fmaxf(redsm[0], redsm[1]), 1e-6f);

    const int lcm2 = max(gc - 2, 0), lcm1 = max(gc - 1, 0);
    const int lcp4 = min(gc + 4, WW - 1), lcp5 = min(gc + 5, WW - 1);
    const bool colv0 = (gc > 0);
    const bool colv5 = (gc + 4 < WW);

    float X[3][8];   // x rows, cols gc-2..gc+5
    float S[3][6];   // score rows, cols gc-1..gc+4

    ldrow8(xc + max(y0 - 2, 0) * WW, gc, lane, lcm2, lcm1, lcp4, lcp5, X[0]);
    ldrow8(xc + max(y0 - 1, 0) * WW, gc, lane, lcm2, lcm1, lcp4, lcp5, X[1]);

    #pragma unroll
    for (int i = 0; i < RSTRIP + 2; i++) {
        const int sr = y0 - 1 + i;                  // score row produced this iter
        const int ry = min(y0 + i, HH - 1);
        ldrow8(xc + ry * WW, gc, lane, lcm2, lcm1, lcp4, lcp5, X[(2 + i) % 3]);
        const float* a = X[i % 3];
        const float* b = X[(i + 1) % 3];
        const float* c = X[(i + 2) % 3];

        float A[8], B[8], C[8];
        #pragma unroll
        for (int k = 0; k < 8; k++) {
            float t = a[k] + c[k];
            A[k] = fmaf(2.0f, b[k], t);
            B[k] = fmaf(-2.0f, b[k], t);
            C[k] = a[k] - c[k];
        }

        const bool srv = (sr >= 0) && (sr < HH);
        float* s = S[i % 3];
        #pragma unroll
        for (int j = 0; j < 6; j++) {               // score cols gc-1+j
            float gxx = fmaf(-2.0f, A[j + 1], A[j] + A[j + 2]);
            float gyy = fmaf(2.0f, B[j + 1], B[j] + B[j + 2]);
            float gxy = C[j + 2] - C[j];
            float sc = fmaxf(fabsf(fmaf(gxx, gyy, -gxy * gxy)), 1e-6f);
            bool valid = srv && (j == 0 ? colv0 : (j == 5 ? colv5 : true));
            s[j] = valid ? sc : -CUDART_INF_F;
        }

        if (i >= 2) {
            const int y = y0 + i - 2;
            // The three S-ring rows are exactly score rows y-1, y, y+1.
            float cm[6];
            #pragma unroll
            for (int k = 0; k < 6; k++)
                cm[k] = fmaxf(fmaxf(S[0][k], S[1][k]), S[2][k]);
            const float* smid = S[(i + 2) % 3];     // score row y
            float ov[4];
            #pragma unroll
            for (int k = 0; k < 4; k++) {
                float p = fmaxf(fmaxf(cm[k], cm[k + 1]), cm[k + 2]);
                float sv = smid[k + 1];
                ov[k] = (sv == p) ? sv * inv : 0.0f;
            }
            float4 o; o.x = ov[0]; o.y = ov[1]; o.z = ov[2]; o.w = ov[3];
            *reinterpret_cast<float4*>(oc + (size_t)y * WW + gc) = o;
        }
    }
}

extern "C" void kernel_launch(void* const* d_in, const int* in_sizes, int n_in,
                              void* d_out, int out_size) {
    const float* x = (const float*)d_in[0];
    float* out = (float*)d_out;

    dim3 mgrd(SLICES, NCH);
    max_kernel<<<mgrd, 128>>>(x);

    dim3 hgrd(HH / RSTRIP, NCH);
    hessian_kernel<<<hgrd, 256>>>(x, out);
}

// round 7
// speedup vs baseline: 1.0052x; 1.0052x over previous
#include <cuda_runtime.h>
#include <math_constants.h>

#define HH 1024
#define WW 1024
#define NCH 48
#define RSTRIP 16
#define SLICES (HH / RSTRIP)   // 64 row-slices per channel

// Per-(channel, row-slice) max of raw |det|. Every slot is written on every
// run by pass 1, so no init kernel and no atomics are needed.
__device__ float g_bmax[NCH * SLICES];

// det = gxx*gyy - gxy^2 reformulated:
//   t = a + c, C = a - c (a=row above, b=center, c=row below)
//   gxx+gyy = 2p,  p = t[j] + t[j+2] - 4 b[j+1]
//   gxx-gyy = 4r,  r = b[j] + b[j+2] - t[j+1]
//   gxx*gyy = p^2 - (2r)^2 ;  gxy = C[j+2] - C[j]

// ---------------------------------------------------------------------------
// Pass 1: per-slice max of raw scores. No NMS, no output stores.
// Each thread: 8 score cols (gc..gc+7); x cols gc-1..gc+8.
// ---------------------------------------------------------------------------
__device__ __forceinline__ void ldrow10(const float* __restrict__ row, int gc,
                                        int lane, float u[10]) {
    float4 m0 = *reinterpret_cast<const float4*>(row + gc);
    float4 m1 = *reinterpret_cast<const float4*>(row + gc + 4);
    u[1] = m0.x; u[2] = m0.y; u[3] = m0.z; u[4] = m0.w;
    u[5] = m1.x; u[6] = m1.y; u[7] = m1.z; u[8] = m1.w;
    u[0] = __shfl_up_sync(0xffffffffu, u[8], 1);
    u[9] = __shfl_down_sync(0xffffffffu, u[1], 1);
    if (lane == 0)  u[0] = row[max(gc - 1, 0)];
    if (lane == 31) u[9] = row[min(gc + 8, WW - 1)];
}

__global__ __launch_bounds__(128, 8)
void max_kernel(const float* __restrict__ x) {
    __shared__ float wmax[4];
    const int ch = blockIdx.y;
    const int y0 = blockIdx.x * RSTRIP;
    const int gc = threadIdx.x * 8;
    const int lane = threadIdx.x & 31;
    const float* __restrict__ xc = x + (size_t)ch * (HH * WW);

    float X[3][10];
    ldrow10(xc + max(y0 - 1, 0) * WW, gc, lane, X[0]);
    ldrow10(xc + y0 * WW, gc, lane, X[1]);

    float m = 0.0f;
    #pragma unroll
    for (int i = 0; i < RSTRIP; i++) {
        const int ry = min(y0 + i + 1, HH - 1);
        ldrow10(xc + ry * WW, gc, lane, X[(i + 2) % 3]);
        const float* a = X[i % 3];
        const float* b = X[(i + 1) % 3];
        const float* c = X[(i + 2) % 3];

        float t[10], C[10];
        #pragma unroll
        for (int k = 0; k < 10; k++) { t[k] = a[k] + c[k]; C[k] = a[k] - c[k]; }

        #pragma unroll
        for (int j = 0; j < 8; j++) {
            float u = t[j] + t[j + 2];
            float p = fmaf(-4.0f, b[j + 1], u);
            float r = (b[j] + b[j + 2]) - t[j + 1];
            float r2 = r + r;
            float gxy = C[j + 2] - C[j];
            float m1 = fmaf(r2, r2, gxy * gxy);
            float det = fmaf(p, p, -m1);
            m = fmaxf(m, fabsf(det));
        }
    }

    #pragma unroll
    for (int off = 16; off > 0; off >>= 1)
        m = fmaxf(m, __shfl_xor_sync(0xffffffffu, m, off));
    if (lane == 0) wmax[threadIdx.x >> 5] = m;
    __syncthreads();
    if (threadIdx.x == 0) {
        m = fmaxf(fmaxf(wmax[0], wmax[1]), fmaxf(wmax[2], wmax[3]));
        g_bmax[ch * SLICES + blockIdx.x] = m;
    }
}

// ---------------------------------------------------------------------------
// Pass 2: scores + separable NMS + normalization, registers only.
// Each thread: 4 output cols (gc..gc+3); x cols gc-2..gc+5.
// ---------------------------------------------------------------------------
__device__ __forceinline__ void ldrow8(const float* __restrict__ row, int gc,
                                       int lane, int lcm2, int lcm1,
                                       int lcp4, int lcp5, float v[8]) {
    float4 m = *reinterpret_cast<const float4*>(row + gc);
    v[2] = m.x; v[3] = m.y; v[4] = m.z; v[5] = m.w;
    v[0] = __shfl_up_sync(0xffffffffu, v[4], 1);
    v[1] = __shfl_up_sync(0xffffffffu, v[5], 1);
    v[6] = __shfl_down_sync(0xffffffffu, v[2], 1);
    v[7] = __shfl_down_sync(0xffffffffu, v[3], 1);
    if (lane == 0)  { v[0] = row[lcm2]; v[1] = row[lcm1]; }
    if (lane == 31) { v[6] = row[lcp4]; v[7] = row[lcp5]; }
}

__global__ __launch_bounds__(256, 6)
void hessian_kernel(const float* __restrict__ x, float* __restrict__ out) {
    __shared__ float redsm[2];
    const int ch = blockIdx.y;
    const int y0 = blockIdx.x * RSTRIP;
    const int gc = threadIdx.x * 4;
    const int lane = threadIdx.x & 31;
    const float* __restrict__ xc = x + (size_t)ch * (HH * WW);
    float* __restrict__ oc = out + (size_t)ch * (HH * WW);

    // Reduce the 64 per-slice maxima for this channel (L2-hit loads).
    if (threadIdx.x < SLICES) {
        float v = g_bmax[ch * SLICES + threadIdx.x];
        #pragma unroll
        for (int off = 16; off > 0; off >>= 1)
            v = fmaxf(v, __shfl_xor_sync(0xffffffffu, v, off));
        if ((threadIdx.x & 31) == 0) redsm[threadIdx.x >> 5] = v;
    }
    __syncthreads();
    const float inv = 1.0f / fmaxf(fmaxf(redsm[0], redsm[1]), 1e-6f);

    const int lcm2 = max(gc - 2, 0), lcm1 = max(gc - 1, 0);
    const int lcp4 = min(gc + 4, WW - 1), lcp5 = min(gc + 5, WW - 1);

    float X[3][8];                 // x rows, cols gc-2..gc+5
    float s1[6], s2[6];            // previous two score rows (cols gc-1..gc+4)
    #pragma unroll
    for (int k = 0; k < 6; k++) { s1[k] = 0.0f; s2[k] = 0.0f; }

    ldrow8(xc + max(y0 - 2, 0) * WW, gc, lane, lcm2, lcm1, lcp4, lcp5, X[0]);
    ldrow8(xc + max(y0 - 1, 0) * WW, gc, lane, lcm2, lcm1, lcp4, lcp5, X[1]);

    #pragma unroll
    for (int i = 0; i < RSTRIP + 2; i++) {
        const int sr = y0 - 1 + i;                  // score row produced this iter
        const int ry = min(y0 + i, HH - 1);
        ldrow8(xc + ry * WW, gc, lane, lcm2, lcm1, lcp4, lcp5, X[(2 + i) % 3]);
        const float* a = X[i % 3];
        const float* b = X[(i + 1) % 3];
        const float* c = X[(i + 2) % 3];

        float t[8], C[8];
        #pragma unroll
        for (int k = 0; k < 8; k++) { t[k] = a[k] + c[k]; C[k] = a[k] - c[k]; }

        float sc6[6];
        #pragma unroll
        for (int j = 0; j < 6; j++) {               // score cols gc-1+j
            float u = t[j] + t[j + 2];
            float p = fmaf(-4.0f, b[j + 1], u);
            float r = (b[j] + b[j + 2]) - t[j + 1];
            float r2 = r + r;
            float gxy = C[j + 2] - C[j];
            float m1 = fmaf(r2, r2, gxy * gxy);
            float det = fmaf(p, p, -m1);
            sc6[j] = fmaxf(fabsf(det), 1e-6f);
        }
        // Column edges: score col -1 (thread 0) / col 1024 (thread 255).
        if (gc == 0)       sc6[0] = -CUDART_INF_F;
        if (gc == WW - 4)  sc6[5] = -CUDART_INF_F;
        // Row edges: only possible at unrolled iters 0 and RSTRIP+1
        // (block-uniform; dead code in the 16 interior copies).
        if ((i == 0 && sr < 0) || (i == RSTRIP + 1 && sr >= HH)) {
            #pragma unroll
            for (int k = 0; k < 6; k++) sc6[k] = -CUDART_INF_F;
        }

        if (i >= 2) {
            const int y = sr - 1;                   // output row
            float cm[6];
            #pragma unroll
            for (int k = 0; k < 6; k++)
                cm[k] = fmaxf(fmaxf(s2[k], s1[k]), sc6[k]);
            float ov[4];
            #pragma unroll
            for (int k = 0; k < 4; k++) {
                float pmax = fmaxf(fmaxf(cm[k], cm[k + 1]), cm[k + 2]);
                float sv = s1[k + 1];
                ov[k] = (sv == pmax) ? sv * inv : 0.0f;
            }
            float4 o; o.x = ov[0]; o.y = ov[1]; o.z = ov[2]; o.w = ov[3];
            *reinterpret_cast<float4*>(oc + (size_t)y * WW + gc) = o;
        }

        #pragma unroll
        for (int k = 0; k < 6; k++) { s2[k] = s1[k]; s1[k] = sc6[k]; }
    }
}

extern "C" void kernel_launch(void* const* d_in, const int* in_sizes, int n_in,
                              void* d_out, int out_size) {
    const float* x = (const float*)d_in[0];
    float* out = (float*)d_out;

    dim3 mgrd(SLICES, NCH);
    max_kernel<<<mgrd, 128>>>(x);

    dim3 hgrd(HH / RSTRIP, NCH);
    hessian_kernel<<<hgrd, 256>>>(x, out);
}